// round 9
// baseline (speedup 1.0000x reference)
#include <cuda_runtime.h>
#include <cuda_bf16.h>
#include <math.h>
#include <stdint.h>

#define NB 32
#define CC 32
#define VV 500
#define TT 96
#define LL 94
#define CO 64
#define GC 96
#define NC_TOT (NB*CC)      // 1024
#define KPAD 512
#define JTOT (VV*LL)        // 47000

typedef unsigned long long u64;

// ---- packed f32x2 helpers (SASS FFMA2) ----
__device__ __forceinline__ u64 pk2(float lo, float hi) {
    u64 r; asm("mov.b64 %0, {%1, %2};" : "=l"(r) : "f"(lo), "f"(hi)); return r;
}
__device__ __forceinline__ void upk2(u64 v, float& lo, float& hi) {
    asm("mov.b64 {%0, %1}, %2;" : "=f"(lo), "=f"(hi) : "l"(v));
}
__device__ __forceinline__ void ffma2(u64& d, u64 a, u64 b) {
    asm("fma.rn.f32x2 %0, %1, %2, %3;" : "=l"(d) : "l"(a), "l"(b), "l"(d));
}

// ---- smem addr + ldmatrix + mma.sync (portable sm_80+ PTX) ----
__device__ __forceinline__ uint32_t smem_u32(const void* p) {
    uint32_t a;
    asm("{ .reg .u64 t; cvta.to.shared.u64 t, %1; cvt.u32.u64 %0, t; }" : "=r"(a) : "l"(p));
    return a;
}
__device__ __forceinline__ uint32_t sw128(uint32_t o) { return o ^ ((o >> 3) & 0x70); }
// swizzle for 256-byte rows: chunk bits [7:4] ^= row bits [11:8]
__device__ __forceinline__ uint32_t sw256(uint32_t o) { return o ^ ((o >> 4) & 0xF0); }

__device__ __forceinline__ void ldsm_x4(uint32_t& a0, uint32_t& a1, uint32_t& a2, uint32_t& a3,
                                        uint32_t addr) {
    asm volatile("ldmatrix.sync.aligned.m8n8.x4.shared.b16 {%0,%1,%2,%3}, [%4];"
                 : "=r"(a0), "=r"(a1), "=r"(a2), "=r"(a3) : "r"(addr));
}
__device__ __forceinline__ void ldsm_x2(uint32_t& b0, uint32_t& b1, uint32_t addr) {
    asm volatile("ldmatrix.sync.aligned.m8n8.x2.shared.b16 {%0,%1}, [%2];"
                 : "=r"(b0), "=r"(b1) : "r"(addr));
}
__device__ __forceinline__ void ldsm_x2t(uint32_t& b0, uint32_t& b1, uint32_t addr) {
    asm volatile("ldmatrix.sync.aligned.m8n8.x2.trans.shared.b16 {%0,%1}, [%2];"
                 : "=r"(b0), "=r"(b1) : "r"(addr));
}
__device__ __forceinline__ void mma16816(float* d, const uint32_t* a, uint32_t b0, uint32_t b1) {
    asm volatile("mma.sync.aligned.m16n8k16.row.col.f32.bf16.bf16.f32 "
                 "{%0,%1,%2,%3},{%4,%5,%6,%7},{%8,%9},{%0,%1,%2,%3};"
                 : "+f"(d[0]), "+f"(d[1]), "+f"(d[2]), "+f"(d[3])
                 : "r"(a[0]), "r"(a[1]), "r"(a[2]), "r"(a[3]), "r"(b0), "r"(b1));
}

// ---- scratch (static device globals; allocation-free) ----
__device__ float g_xt[48128000];   // (nc, v, l) fp32 (feeds prepX)
__device__ float g_A2[VV * VV];
__device__ __align__(16) __nv_bfloat16 g_ATh[KPAD * KPAD];   // [w][v] hi
__device__ __align__(16) __nv_bfloat16 g_ATl[KPAD * KPAD];
__device__ __align__(16) __nv_bfloat16 g_BTh[KPAD * KPAD];   // A2
__device__ __align__(16) __nv_bfloat16 g_BTl[KPAD * KPAD];
__device__ __align__(16) __nv_bfloat16 g_Xh[(size_t)NC_TOT * 96 * KPAD]; // [nc][l][v]
__device__ __align__(16) __nv_bfloat16 g_Xl[(size_t)NC_TOT * 96 * KPAD];
// concat H = [xt; x1; x2] as bf16 hi/lo: [n][k=96][j=v*94+l]
__device__ __align__(16) __nv_bfloat16 g_Hh[(size_t)NB * GC * JTOT];
__device__ __align__(16) __nv_bfloat16 g_Hl[(size_t)NB * GC * JTOT];
__device__ __align__(16) __nv_bfloat16 g_Wh[CO * GC];
__device__ __align__(16) __nv_bfloat16 g_Wl[CO * GC];

__device__ __forceinline__ void wr_split2(size_t off, float a, float b) {
    __nv_bfloat16 ha = __float2bfloat16(a), hb = __float2bfloat16(b);
    __nv_bfloat16 la = __float2bfloat16(a - __bfloat162float(ha));
    __nv_bfloat16 lb = __float2bfloat16(b - __bfloat162float(hb));
    *(__nv_bfloat162*)(g_Hh + off) = __halves2bfloat162(ha, hb);
    *(__nv_bfloat162*)(g_Hl + off) = __halves2bfloat162(la, lb);
}

// ---------------------------------------------------------------------------
// K0: A2 = A @ A
// ---------------------------------------------------------------------------
__global__ void __launch_bounds__(256) k_a2(const float* __restrict__ A)
{
    __shared__ __align__(16) float Ls[16][64];
    __shared__ __align__(16) float Rs[16][64];
    int rb = blockIdx.y * 64, wb = blockIdx.x * 64;
    int t = threadIdx.x;
    int tr = t >> 4, tw = t & 15;
    float acc[4][4];
#pragma unroll
    for (int i = 0; i < 4; i++)
#pragma unroll
        for (int j = 0; j < 4; j++) acc[i][j] = 0.f;

    for (int ub = 0; ub < 512; ub += 16) {
#pragma unroll
        for (int j = 0; j < 4; j++) {
            int e = t + j * 256;
            int uu = e & 15, r = e >> 4;
            int gr = rb + r, gu = ub + uu;
            Ls[uu][r] = (gr < VV && gu < VV) ? A[gr * VV + gu] : 0.f;
            int w = e & 63, uu2 = e >> 6;
            int gu2 = ub + uu2, gw = wb + w;
            Rs[uu2][w] = (gu2 < VV && gw < VV) ? A[gu2 * VV + gw] : 0.f;
        }
        __syncthreads();
#pragma unroll
        for (int uu = 0; uu < 16; uu++) {
            float4 lv = *(const float4*)&Ls[uu][tr * 4];
            float4 rv = *(const float4*)&Rs[uu][tw * 4];
            float l[4] = {lv.x, lv.y, lv.z, lv.w};
            float r[4] = {rv.x, rv.y, rv.z, rv.w};
#pragma unroll
            for (int i = 0; i < 4; i++)
#pragma unroll
                for (int j = 0; j < 4; j++) acc[i][j] += l[i] * r[j];
        }
        __syncthreads();
    }
#pragma unroll
    for (int i = 0; i < 4; i++) {
        int r = rb + tr * 4 + i;
        if (r < VV) {
#pragma unroll
            for (int j = 0; j < 4; j++) {
                int w = wb + tw * 4 + j;
                if (w < VV) g_A2[r * VV + w] = acc[i][j];
            }
        }
    }
}

// ---------------------------------------------------------------------------
// prepA: transposed, zero-padded bf16 hi/lo of A and A2: [w(512)][v(512)]
// ---------------------------------------------------------------------------
__global__ void __launch_bounds__(256) k_prepA(const float* __restrict__ A)
{
    int idx = blockIdx.x * 256 + threadIdx.x;
    if (idx >= KPAD * KPAD) return;
    int w = idx >> 9, v = idx & 511;
    bool ok = (v < VV) && (w < VV);
    float a = ok ? A[v * VV + w] : 0.f;
    float b = ok ? g_A2[v * VV + w] : 0.f;
    __nv_bfloat16 ah = __float2bfloat16(a);
    g_ATh[idx] = ah;
    g_ATl[idx] = __float2bfloat16(a - __bfloat162float(ah));
    __nv_bfloat16 bh = __float2bfloat16(b);
    g_BTh[idx] = bh;
    g_BTl[idx] = __float2bfloat16(b - __bfloat162float(bh));
}

// prepW: bf16 hi/lo of w_out [o][96]
__global__ void __launch_bounds__(256) k_prepW(const float* __restrict__ w_out)
{
    int e = blockIdx.x * 256 + threadIdx.x;
    if (e >= CO * GC) return;
    float v = w_out[e];
    __nv_bfloat16 h = __float2bfloat16(v);
    g_Wh[e] = h;
    g_Wl[e] = __float2bfloat16(v - __bfloat162float(h));
}

// ---------------------------------------------------------------------------
// K1: gated temporal conv (FFMA2) -> g_xt fp32 + H rows 0..31 (bf16 hi/lo)
// ---------------------------------------------------------------------------
__global__ void __launch_bounds__(256) k_tconv(const float* __restrict__ x,
    const float* __restrict__ w1, const float* __restrict__ b1,
    const float* __restrict__ w2, const float* __restrict__ b2,
    const float* __restrict__ w3, const float* __restrict__ b3)
{
    __shared__ __align__(16) float xs[CC][TT];
    __shared__ __align__(16) float ws[3][CC * 3 * CC];
    int nv = blockIdx.x;
    int n = nv / VV, v = nv - n * VV;
    int t = threadIdx.x;
    const float* xb = x + ((size_t)n * CC * VV + v) * TT;
    for (int e = t; e < CC * TT; e += 256) {
        int i = e / TT, tt = e - i * TT;
        xs[i][tt] = xb[(size_t)i * VV * TT + tt];
    }
    for (int e = t; e < CC * CC * 3; e += 256) {
        int c = e & 31;
        int ik = e >> 5;
        int i = ik / 3, k = ik - i * 3;
        int gi = (c * CC + i) * 3 + k;
        ws[0][e] = w1[gi];
        ws[1][e] = w2[gi];
        ws[2][e] = w3[gi];
    }
    __syncthreads();

    int c = t & 31, grp = t >> 5;
    int lb = grp * 12;
    u64 a1p[6], a2p[6], a3p[6];
#pragma unroll
    for (int j = 0; j < 6; j++) { a1p[j] = 0ULL; a2p[j] = 0ULL; a3p[j] = 0ULL; }

#pragma unroll 2
    for (int i = 0; i < CC; i++) {
        float xv[14];
#pragma unroll
        for (int j = 0; j < 14; j++)
            xv[j] = (lb + j < TT) ? xs[i][lb + j] : 0.f;
        u64 pa[7], pb[6];
#pragma unroll
        for (int j = 0; j < 7; j++) pa[j] = pk2(xv[2 * j], xv[2 * j + 1]);
#pragma unroll
        for (int j = 0; j < 6; j++) pb[j] = pk2(xv[2 * j + 1], xv[2 * j + 2]);
#pragma unroll
        for (int k = 0; k < 3; k++) {
            int wi = (i * 3 + k) * 32 + c;
            float wa = ws[0][wi], wb = ws[1][wi], wc = ws[2][wi];
            u64 wap = pk2(wa, wa), wbp = pk2(wb, wb), wcp = pk2(wc, wc);
#pragma unroll
            for (int j = 0; j < 6; j++) {
                u64 xp = (k == 0) ? pa[j] : (k == 1) ? pb[j] : pa[j + 1];
                ffma2(a1p[j], wap, xp);
                ffma2(a2p[j], wbp, xp);
                ffma2(a3p[j], wcp, xp);
            }
        }
    }
    float bb1 = b1[c], bb2 = b2[c], bb3 = b3[c];
    float* xo = g_xt + ((size_t)(n * CC + c) * VV + v) * LL;
    size_t hbase = (size_t)(n * GC + c) * JTOT + (size_t)v * LL;
#pragma unroll
    for (int j = 0; j < 6; j++) {
        float a1lo, a1hi, a2lo, a2hi, a3lo, a3hi;
        upk2(a1p[j], a1lo, a1hi);
        upk2(a2p[j], a2lo, a2hi);
        upk2(a3p[j], a3lo, a3hi);
        int l0 = lb + 2 * j;
        if (l0 < LL) {
            float z2a = a2lo + bb2;
            float sga = 1.f / (1.f + __expf(-z2a));
            float r0 = fmaxf(a1lo + bb1 + sga + a3lo + bb3, 0.f);
            float z2b = a2hi + bb2;
            float sgb = 1.f / (1.f + __expf(-z2b));
            float r1 = fmaxf(a1hi + bb1 + sgb + a3hi + bb3, 0.f);
            xo[l0] = r0;
            xo[l0 + 1] = r1;
            wr_split2(hbase + l0, r0, r1);
        }
    }
}

// ---------------------------------------------------------------------------
// prepX: transpose + bf16 hi/lo split of xt: [nc][l(96 pad)][v(512 pad)]
// ---------------------------------------------------------------------------
__global__ void __launch_bounds__(256) k_prepX()
{
    __shared__ float tile[32][33];
    int nc = blockIdx.x;
    int t = threadIdx.x;
    int tr = t >> 5, tc = t & 31;
    for (int lt = 0; lt < 3; lt++) {
        for (int vt = 0; vt < 16; vt++) {
            __syncthreads();
#pragma unroll
            for (int r = 0; r < 4; r++) {
                int vv = vt * 32 + tr + r * 8;
                int l = lt * 32 + tc;
                float val = (vv < VV && l < LL) ? g_xt[((size_t)nc * VV + vv) * LL + l] : 0.f;
                tile[tr + r * 8][tc] = val;
            }
            __syncthreads();
#pragma unroll
            for (int r = 0; r < 4; r++) {
                int l = lt * 32 + tr + r * 8;
                int vv = vt * 32 + tc;
                float val = tile[tc][tr + r * 8];
                __nv_bfloat16 h = __float2bfloat16(val);
                float lo = val - __bfloat162float(h);
                size_t o = ((size_t)nc * 96 + l) * KPAD + vv;
                g_Xh[o] = h;
                g_Xl[o] = __float2bfloat16(lo);
            }
        }
    }
}

// ---------------------------------------------------------------------------
// K2: mma.sync bf16-split diffusion -> H rows 32..95 (bf16 hi/lo)
// ---------------------------------------------------------------------------
#define SM_AH   0
#define SM_AL   16384
#define SM_BH   32768
#define SM_BL   49152
#define SM_XH   65536
#define SM_XL   77824
#define SM_DIFF_TOTAL 90112

__device__ __forceinline__ void ld_tile(char* smem, uint32_t off,
                                        const __nv_bfloat16* g, size_t rowbase,
                                        int nrows, int kb, int t)
{
    const uint4* gp = (const uint4*)g;
    for (int e = t; e < nrows * 8; e += 512) {
        int m = e >> 3, c8 = e & 7;
        uint4 v = gp[(((rowbase + m) * KPAD + kb) >> 3) + c8];
        uint32_t bo = (uint32_t)m * 128 + c8 * 16;
        *(uint4*)(smem + off + sw128(bo)) = v;
    }
}

__global__ void __launch_bounds__(512, 1) k_diff_mma()
{
    extern __shared__ char smem[];
    uint32_t sb = smem_u32(smem);
    int t = threadIdx.x;
    int wid = t >> 5, lane = t & 31;
    int wt = blockIdx.x;            // 0..3
    int nc = blockIdx.y;            // 0..1023
    int wbase = wt * 128;

    int mat = wid >> 3;             // 0: A -> x1, 1: A2 -> x2
    int nw  = (wid >> 2) & 1;       // n-group of 48
    int mw  = wid & 3;              // m-group of 32

    uint32_t aHbase = sb + (mat ? SM_BH : SM_AH);
    uint32_t aLbase = sb + (mat ? SM_BL : SM_AL);
    uint32_t xHbase = sb + SM_XH;
    uint32_t xLbase = sb + SM_XL;

    uint32_t aRow = (uint32_t)(mw * 32 + (lane & 15));
    uint32_t aKH  = (uint32_t)((lane >> 4) * 16);
    uint32_t xRow = (uint32_t)(nw * 48 + (lane & 7));
    uint32_t xKH  = (uint32_t)(((lane >> 3) & 1) * 16);

    float acc[2][6][4];
#pragma unroll
    for (int mi = 0; mi < 2; mi++)
#pragma unroll
        for (int ni = 0; ni < 6; ni++)
#pragma unroll
            for (int r = 0; r < 4; r++) acc[mi][ni][r] = 0.f;

    for (int s = 0; s < 8; s++) {
        int kb = s * 64;
        ld_tile(smem, SM_AH, g_ATh, (size_t)wbase, 128, kb, t);
        ld_tile(smem, SM_AL, g_ATl, (size_t)wbase, 128, kb, t);
        ld_tile(smem, SM_BH, g_BTh, (size_t)wbase, 128, kb, t);
        ld_tile(smem, SM_BL, g_BTl, (size_t)wbase, 128, kb, t);
        ld_tile(smem, SM_XH, g_Xh, (size_t)nc * 96, 96, kb, t);
        ld_tile(smem, SM_XL, g_Xl, (size_t)nc * 96, 96, kb, t);
        __syncthreads();

#pragma unroll
        for (int ks = 0; ks < 4; ks++) {
            uint32_t kbyte = (uint32_t)(ks * 32);
            uint32_t ah[2][4], al[2][4];
#pragma unroll
            for (int mi = 0; mi < 2; mi++) {
                uint32_t bo = (aRow + mi * 16) * 128 + kbyte + aKH;
                uint32_t swo = sw128(bo);
                ldsm_x4(ah[mi][0], ah[mi][1], ah[mi][2], ah[mi][3], aHbase + swo);
                ldsm_x4(al[mi][0], al[mi][1], al[mi][2], al[mi][3], aLbase + swo);
            }
#pragma unroll
            for (int ni = 0; ni < 6; ni++) {
                uint32_t bo = (xRow + ni * 8) * 128 + kbyte + xKH;
                uint32_t swo = sw128(bo);
                uint32_t xh0, xh1, xl0, xl1;
                ldsm_x2(xh0, xh1, xHbase + swo);
                ldsm_x2(xl0, xl1, xLbase + swo);
#pragma unroll
                for (int mi = 0; mi < 2; mi++) {
                    mma16816(acc[mi][ni], ah[mi], xh0, xh1);
                    mma16816(acc[mi][ni], ah[mi], xl0, xl1);
                    mma16816(acc[mi][ni], al[mi], xh0, xh1);
                }
            }
        }
        __syncthreads();
    }

    // epilogue -> H rows (bf16 hi/lo split)
    int n = nc >> 5, ch = nc & 31;
    size_t hrow = (size_t)(n * GC + (mat ? 64 : 32) + ch) * JTOT;
    int r = lane >> 2, c = (lane & 3) * 2;
#pragma unroll
    for (int mi = 0; mi < 2; mi++) {
        int w0 = wbase + mw * 32 + mi * 16 + r;
#pragma unroll
        for (int ni = 0; ni < 6; ni++) {
            int l0 = nw * 48 + ni * 8 + c;
            if (l0 < LL) {
                if (w0 < VV)
                    wr_split2(hrow + (size_t)w0 * LL + l0, acc[mi][ni][0], acc[mi][ni][1]);
                int w1 = w0 + 8;
                if (w1 < VV)
                    wr_split2(hrow + (size_t)w1 * LL + l0, acc[mi][ni][2], acc[mi][ni][3]);
            }
        }
    }
}

// ---------------------------------------------------------------------------
// K3: projection via mma.sync. out[o][j] = prelu(W[o,:96] . H[:,j] + b[o])
// block: 256 thr / 8 warps, tile = 64o x 128j per (jb, n).
// warp = (mt = wid&3 -> 16 o's, nhalf = wid>>2 -> 64 j's).
// ---------------------------------------------------------------------------
#define PJ 128
#define SMP_HH  0
#define SMP_HL  24576
#define SMP_WH  49152
#define SMP_WL  61440
#define SM_PROJ_TOTAL 73728
#define WS 192   // W smem row bytes (96 bf16)

__global__ void __launch_bounds__(256, 1) k_proj_mma(
    const float* __restrict__ b_out, const float* __restrict__ prelu_a,
    float* __restrict__ out)
{
    extern __shared__ char smem[];
    uint32_t sb = smem_u32(smem);
    int t = threadIdx.x;
    int wid = t >> 5, lane = t & 31;
    int jb = blockIdx.x * PJ;
    int n = blockIdx.y;

    // stage W hi/lo (rows [o][k], 192B rows)
    for (int e = t; e < CO * GC; e += 256) {
        int o = e / GC, k = e - o * GC;
        *(__nv_bfloat16*)(smem + SMP_WH + o * WS + k * 2) = g_Wh[e];
        *(__nv_bfloat16*)(smem + SMP_WL + o * WS + k * 2) = g_Wl[e];
    }
    // stage H hi/lo [96][128j] in 256B swizzled rows
    for (int e = t; e < GC * 16; e += 256) {
        int k = e >> 4, c16 = e & 15;
        int j0 = jb + c16 * 8;
        size_t gb = (size_t)(n * GC + k) * JTOT + j0;
        uint32_t so = sw256((uint32_t)k * 256 + c16 * 16);
        if (j0 + 7 < JTOT) {
            *(uint4*)(smem + SMP_HH + so) = *(const uint4*)(g_Hh + gb);
            *(uint4*)(smem + SMP_HL + so) = *(const uint4*)(g_Hl + gb);
        } else {
            __nv_bfloat16 th[8], tl[8];
#pragma unroll
            for (int i = 0; i < 8; i++) {
                bool ok = (j0 + i) < JTOT;
                th[i] = ok ? g_Hh[gb + i] : __float2bfloat16(0.f);
                tl[i] = ok ? g_Hl[gb + i] : __float2bfloat16(0.f);
            }
            *(uint4*)(smem + SMP_HH + so) = *(uint4*)th;
            *(uint4*)(smem + SMP_HL + so) = *(uint4*)tl;
        }
    }
    __syncthreads();

    int mt = wid & 3, nhalf = wid >> 2;

    // preload W fragments (m16k16, 6 ksteps, hi+lo)
    uint32_t wAddrRow = (uint32_t)(mt * 16 + (lane & 15)) * WS + ((lane >> 4) * 16);
    uint32_t ahf[6][4], alf[6][4];
#pragma unroll
    for (int kt = 0; kt < 6; kt++) {
        uint32_t ad = wAddrRow + kt * 32;
        ldsm_x4(ahf[kt][0], ahf[kt][1], ahf[kt][2], ahf[kt][3], sb + SMP_WH + ad);
        ldsm_x4(alf[kt][0], alf[kt][1], alf[kt][2], alf[kt][3], sb + SMP_WL + ad);
    }

    float acc[8][4];
#pragma unroll
    for (int i = 0; i < 8; i++)
#pragma unroll
        for (int r = 0; r < 4; r++) acc[i][r] = 0.f;

    uint32_t bRow = (uint32_t)(lane & 15);   // k row within kstep
#pragma unroll
    for (int kt = 0; kt < 6; kt++) {
        uint32_t krow = (uint32_t)(kt * 16) + bRow;
#pragma unroll
        for (int nt = 0; nt < 8; nt++) {
            uint32_t bo = sw256(krow * 256 + (uint32_t)(nhalf * 64 + nt * 8) * 2);
            uint32_t bh0, bh1, bl0, bl1;
            ldsm_x2t(bh0, bh1, sb + SMP_HH + bo);
            ldsm_x2t(bl0, bl1, sb + SMP_HL + bo);
            mma16816(acc[nt], ahf[kt], bh0, bh1);
            mma16816(acc[nt], ahf[kt], bl0, bl1);
            mma16816(acc[nt], alf[kt], bh0, bh1);
        }
    }

    // epilogue: bias + PReLU
    float pa = prelu_a[0];
    int r = lane >> 2, cc = (lane & 3) * 2;
    int o0 = mt * 16 + r, o1 = o0 + 8;
    float bo0 = b_out[o0], bo1 = b_out[o1];
    float* ob0 = out + (size_t)(n * CO + o0) * JTOT;
    float* ob1 = out + (size_t)(n * CO + o1) * JTOT;
#pragma unroll
    for (int nt = 0; nt < 8; nt++) {
        int j0 = jb + nhalf * 64 + nt * 8 + cc;
        if (j0 < JTOT) {
            float p0 = acc[nt][0] + bo0;
            float p1 = acc[nt][1] + bo0;
            *(float2*)&ob0[j0] = make_float2(p0 > 0.f ? p0 : pa * p0,
                                             p1 > 0.f ? p1 : pa * p1);
            float p2 = acc[nt][2] + bo1;
            float p3 = acc[nt][3] + bo1;
            *(float2*)&ob1[j0] = make_float2(p2 > 0.f ? p2 : pa * p2,
                                             p3 > 0.f ? p3 : pa * p3);
        }
    }
}

// ---------------------------------------------------------------------------
extern "C" void kernel_launch(void* const* d_in, const int* in_sizes, int n_in,
                              void* d_out, int out_size)
{
    const float* x  = (const float*)d_in[0];
    const float* A  = (const float*)d_in[1];
    const float* w1 = (const float*)d_in[2];
    const float* b1 = (const float*)d_in[3];
    const float* w2 = (const float*)d_in[4];
    const float* b2 = (const float*)d_in[5];
    const float* w3 = (const float*)d_in[6];
    const float* b3 = (const float*)d_in[7];
    const float* wo = (const float*)d_in[8];
    const float* bo = (const float*)d_in[9];
    const float* pa = (const float*)d_in[10];
    float* out = (float*)d_out;

    static int smem_set = 0;
    if (!smem_set) {
        cudaFuncSetAttribute(k_diff_mma, cudaFuncAttributeMaxDynamicSharedMemorySize,
                             SM_DIFF_TOTAL);
        cudaFuncSetAttribute(k_proj_mma, cudaFuncAttributeMaxDynamicSharedMemorySize,
                             SM_PROJ_TOTAL);
        smem_set = 1;
    }

    k_a2<<<dim3(8, 8), 256>>>(A);
    k_prepA<<<(KPAD * KPAD) / 256, 256>>>(A);
    k_prepW<<<(CO * GC + 255) / 256, 256>>>(wo);
    k_tconv<<<NB * VV, 256>>>(x, w1, b1, w2, b2, w3, b3);
    k_prepX<<<NC_TOT, 256>>>();
    k_diff_mma<<<dim3(4, NC_TOT), 512, SM_DIFF_TOTAL>>>();
    k_proj_mma<<<dim3((JTOT + PJ - 1) / PJ, NB), 256, SM_PROJ_TOTAL>>>(bo, pa, out);
}

// round 11
// speedup vs baseline: 1.2715x; 1.2715x over previous
#include <cuda_runtime.h>
#include <cuda_bf16.h>
#include <math.h>
#include <stdint.h>

#define NB 32
#define CC 32
#define VV 500
#define TT 96
#define LL 94
#define CO 64
#define GC 96
#define NC_TOT (NB*CC)      // 1024
#define KPAD 512
#define JTOT (VV*LL)        // 47000

typedef unsigned long long u64;

// ---- packed f32x2 helpers (SASS FFMA2) ----
__device__ __forceinline__ u64 pk2(float lo, float hi) {
    u64 r; asm("mov.b64 %0, {%1, %2};" : "=l"(r) : "f"(lo), "f"(hi)); return r;
}
__device__ __forceinline__ void upk2(u64 v, float& lo, float& hi) {
    asm("mov.b64 {%0, %1}, %2;" : "=f"(lo), "=f"(hi) : "l"(v));
}
__device__ __forceinline__ void ffma2(u64& d, u64 a, u64 b) {
    asm("fma.rn.f32x2 %0, %1, %2, %3;" : "=l"(d) : "l"(a), "l"(b), "l"(d));
}

// ---- smem addr + ldmatrix + mma.sync + cp.async (portable sm_80+ PTX) ----
__device__ __forceinline__ uint32_t smem_u32(const void* p) {
    uint32_t a;
    asm("{ .reg .u64 t; cvta.to.shared.u64 t, %1; cvt.u32.u64 %0, t; }" : "=r"(a) : "l"(p));
    return a;
}
__device__ __forceinline__ uint32_t sw128(uint32_t o) { return o ^ ((o >> 3) & 0x70); }

__device__ __forceinline__ void ldsm_x4(uint32_t& a0, uint32_t& a1, uint32_t& a2, uint32_t& a3,
                                        uint32_t addr) {
    asm volatile("ldmatrix.sync.aligned.m8n8.x4.shared.b16 {%0,%1,%2,%3}, [%4];"
                 : "=r"(a0), "=r"(a1), "=r"(a2), "=r"(a3) : "r"(addr));
}
__device__ __forceinline__ void ldsm_x2(uint32_t& b0, uint32_t& b1, uint32_t addr) {
    asm volatile("ldmatrix.sync.aligned.m8n8.x2.shared.b16 {%0,%1}, [%2];"
                 : "=r"(b0), "=r"(b1) : "r"(addr));
}
__device__ __forceinline__ void mma16816(float* d, const uint32_t* a, uint32_t b0, uint32_t b1) {
    asm volatile("mma.sync.aligned.m16n8k16.row.col.f32.bf16.bf16.f32 "
                 "{%0,%1,%2,%3},{%4,%5,%6,%7},{%8,%9},{%0,%1,%2,%3};"
                 : "+f"(d[0]), "+f"(d[1]), "+f"(d[2]), "+f"(d[3])
                 : "r"(a[0]), "r"(a[1]), "r"(a[2]), "r"(a[3]), "r"(b0), "r"(b1));
}
__device__ __forceinline__ void cpa16(uint32_t dst, const void* src) {
    asm volatile("cp.async.cg.shared.global [%0], [%1], 16;" :: "r"(dst), "l"(src));
}

// ---- scratch (static device globals; allocation-free) ----
__device__ float g_xt[48128000];   // (nc, v, l) fp32
__device__ float g_x1[48128000];
__device__ float g_x2[48128000];
__device__ float g_A2[VV * VV];
__device__ __align__(16) __nv_bfloat16 g_ATh[KPAD * KPAD];   // [w][v] hi
__device__ __align__(16) __nv_bfloat16 g_ATl[KPAD * KPAD];
__device__ __align__(16) __nv_bfloat16 g_BTh[KPAD * KPAD];   // A2
__device__ __align__(16) __nv_bfloat16 g_BTl[KPAD * KPAD];
__device__ __align__(16) __nv_bfloat16 g_Xh[(size_t)NC_TOT * 96 * KPAD]; // [nc][l][v]
__device__ __align__(16) __nv_bfloat16 g_Xl[(size_t)NC_TOT * 96 * KPAD];

// ---------------------------------------------------------------------------
// K0: A2 = A @ A
// ---------------------------------------------------------------------------
__global__ void __launch_bounds__(256) k_a2(const float* __restrict__ A)
{
    __shared__ __align__(16) float Ls[16][64];
    __shared__ __align__(16) float Rs[16][64];
    int rb = blockIdx.y * 64, wb = blockIdx.x * 64;
    int t = threadIdx.x;
    int tr = t >> 4, tw = t & 15;
    float acc[4][4];
#pragma unroll
    for (int i = 0; i < 4; i++)
#pragma unroll
        for (int j = 0; j < 4; j++) acc[i][j] = 0.f;

    for (int ub = 0; ub < 512; ub += 16) {
#pragma unroll
        for (int j = 0; j < 4; j++) {
            int e = t + j * 256;
            int uu = e & 15, r = e >> 4;
            int gr = rb + r, gu = ub + uu;
            Ls[uu][r] = (gr < VV && gu < VV) ? A[gr * VV + gu] : 0.f;
            int w = e & 63, uu2 = e >> 6;
            int gu2 = ub + uu2, gw = wb + w;
            Rs[uu2][w] = (gu2 < VV && gw < VV) ? A[gu2 * VV + gw] : 0.f;
        }
        __syncthreads();
#pragma unroll
        for (int uu = 0; uu < 16; uu++) {
            float4 lv = *(const float4*)&Ls[uu][tr * 4];
            float4 rv = *(const float4*)&Rs[uu][tw * 4];
            float l[4] = {lv.x, lv.y, lv.z, lv.w};
            float r[4] = {rv.x, rv.y, rv.z, rv.w};
#pragma unroll
            for (int i = 0; i < 4; i++)
#pragma unroll
                for (int j = 0; j < 4; j++) acc[i][j] += l[i] * r[j];
        }
        __syncthreads();
    }
#pragma unroll
    for (int i = 0; i < 4; i++) {
        int r = rb + tr * 4 + i;
        if (r < VV) {
#pragma unroll
            for (int j = 0; j < 4; j++) {
                int w = wb + tw * 4 + j;
                if (w < VV) g_A2[r * VV + w] = acc[i][j];
            }
        }
    }
}

// ---------------------------------------------------------------------------
// prepA: transposed, zero-padded bf16 hi/lo of A and A2: [w(512)][v(512)]
// ---------------------------------------------------------------------------
__global__ void __launch_bounds__(256) k_prepA(const float* __restrict__ A)
{
    int idx = blockIdx.x * 256 + threadIdx.x;
    if (idx >= KPAD * KPAD) return;
    int w = idx >> 9, v = idx & 511;
    bool ok = (v < VV) && (w < VV);
    float a = ok ? A[v * VV + w] : 0.f;
    float b = ok ? g_A2[v * VV + w] : 0.f;
    __nv_bfloat16 ah = __float2bfloat16(a);
    g_ATh[idx] = ah;
    g_ATl[idx] = __float2bfloat16(a - __bfloat162float(ah));
    __nv_bfloat16 bh = __float2bfloat16(b);
    g_BTh[idx] = bh;
    g_BTl[idx] = __float2bfloat16(b - __bfloat162float(bh));
}

// ---------------------------------------------------------------------------
// K1: gated temporal conv (FFMA2) -> g_xt [nc][v][l]
// ---------------------------------------------------------------------------
__global__ void __launch_bounds__(256) k_tconv(const float* __restrict__ x,
    const float* __restrict__ w1, const float* __restrict__ b1,
    const float* __restrict__ w2, const float* __restrict__ b2,
    const float* __restrict__ w3, const float* __restrict__ b3)
{
    __shared__ __align__(16) float xs[CC][TT];
    __shared__ __align__(16) float ws[3][CC * 3 * CC];
    int nv = blockIdx.x;
    int n = nv / VV, v = nv - n * VV;
    int t = threadIdx.x;
    const float* xb = x + ((size_t)n * CC * VV + v) * TT;
    for (int e = t; e < CC * TT; e += 256) {
        int i = e / TT, tt = e - i * TT;
        xs[i][tt] = xb[(size_t)i * VV * TT + tt];
    }
    for (int e = t; e < CC * CC * 3; e += 256) {
        int c = e & 31;
        int ik = e >> 5;
        int i = ik / 3, k = ik - i * 3;
        int gi = (c * CC + i) * 3 + k;
        ws[0][e] = w1[gi];
        ws[1][e] = w2[gi];
        ws[2][e] = w3[gi];
    }
    __syncthreads();

    int c = t & 31, grp = t >> 5;
    int lb = grp * 12;
    u64 a1p[6], a2p[6], a3p[6];
#pragma unroll
    for (int j = 0; j < 6; j++) { a1p[j] = 0ULL; a2p[j] = 0ULL; a3p[j] = 0ULL; }

#pragma unroll 2
    for (int i = 0; i < CC; i++) {
        float xv[14];
#pragma unroll
        for (int j = 0; j < 14; j++)
            xv[j] = (lb + j < TT) ? xs[i][lb + j] : 0.f;
        u64 pa[7], pb[6];
#pragma unroll
        for (int j = 0; j < 7; j++) pa[j] = pk2(xv[2 * j], xv[2 * j + 1]);
#pragma unroll
        for (int j = 0; j < 6; j++) pb[j] = pk2(xv[2 * j + 1], xv[2 * j + 2]);
#pragma unroll
        for (int k = 0; k < 3; k++) {
            int wi = (i * 3 + k) * 32 + c;
            float wa = ws[0][wi], wb = ws[1][wi], wc = ws[2][wi];
            u64 wap = pk2(wa, wa), wbp = pk2(wb, wb), wcp = pk2(wc, wc);
#pragma unroll
            for (int j = 0; j < 6; j++) {
                u64 xp = (k == 0) ? pa[j] : (k == 1) ? pb[j] : pa[j + 1];
                ffma2(a1p[j], wap, xp);
                ffma2(a2p[j], wbp, xp);
                ffma2(a3p[j], wcp, xp);
            }
        }
    }
    float bb1 = b1[c], bb2 = b2[c], bb3 = b3[c];
    float* xo = g_xt + ((size_t)(n * CC + c) * VV + v) * LL;
#pragma unroll
    for (int j = 0; j < 6; j++) {
        float a1lo, a1hi, a2lo, a2hi, a3lo, a3hi;
        upk2(a1p[j], a1lo, a1hi);
        upk2(a2p[j], a2lo, a2hi);
        upk2(a3p[j], a3lo, a3hi);
        int l0 = lb + 2 * j;
        if (l0 < LL) {
            float z2 = a2lo + bb2;
            float sg = 1.f / (1.f + __expf(-z2));
            float tv = a1lo + bb1 + sg + a3lo + bb3;
            xo[l0] = fmaxf(tv, 0.f);
        }
        int l1 = l0 + 1;
        if (l1 < LL) {
            float z2 = a2hi + bb2;
            float sg = 1.f / (1.f + __expf(-z2));
            float tv = a1hi + bb1 + sg + a3hi + bb3;
            xo[l1] = fmaxf(tv, 0.f);
        }
    }
}

// ---------------------------------------------------------------------------
// prepX: transpose + bf16 hi/lo split of xt: [nc][l(96 pad)][v(512 pad)]
// ---------------------------------------------------------------------------
__global__ void __launch_bounds__(256) k_prepX()
{
    __shared__ float tile[32][33];
    int nc = blockIdx.x;
    int t = threadIdx.x;
    int tr = t >> 5, tc = t & 31;
    for (int lt = 0; lt < 3; lt++) {
        for (int vt = 0; vt < 16; vt++) {
            __syncthreads();
#pragma unroll
            for (int r = 0; r < 4; r++) {
                int vv = vt * 32 + tr + r * 8;
                int l = lt * 32 + tc;
                float val = (vv < VV && l < LL) ? g_xt[((size_t)nc * VV + vv) * LL + l] : 0.f;
                tile[tr + r * 8][tc] = val;
            }
            __syncthreads();
#pragma unroll
            for (int r = 0; r < 4; r++) {
                int l = lt * 32 + tr + r * 8;
                int vv = vt * 32 + tc;
                float val = tile[tc][tr + r * 8];
                __nv_bfloat16 h = __float2bfloat16(val);
                float lo = val - __bfloat162float(h);
                size_t o = ((size_t)nc * 96 + l) * KPAD + vv;
                g_Xh[o] = h;
                g_Xl[o] = __float2bfloat16(lo);
            }
        }
    }
}

// ---------------------------------------------------------------------------
// K2: mma.sync bf16-split diffusion, cp.async double-buffered.
// CTA = (w-tile 128, nc). D[w,l] = sum_v AT[w,v]*XT[l,v] for A and A2.
// 512 thr / 16 warps: warp = (mat, n-half of 48, m-group of 32).
// ---------------------------------------------------------------------------
#define SM_AH   0
#define SM_AL   16384
#define SM_BH   32768
#define SM_BL   49152
#define SM_XH   65536
#define SM_XL   77824
#define SM_STAGE 90112
#define SM_DIFF_TOTAL (2 * SM_STAGE)   // 180224

__device__ __forceinline__ void cp_tile(uint32_t dstbase,
                                        const __nv_bfloat16* g, size_t rowbase,
                                        int nrows, int kb, int t)
{
    const uint4* gp = (const uint4*)g;
    for (int e = t; e < nrows * 8; e += 512) {
        int m = e >> 3, c8 = e & 7;
        const uint4* src = gp + (((rowbase + m) * KPAD + kb) >> 3) + c8;
        uint32_t bo = (uint32_t)m * 128 + c8 * 16;
        cpa16(dstbase + sw128(bo), src);
    }
}

__global__ void __launch_bounds__(512, 1) k_diff_mma()
{
    extern __shared__ char smem[];
    uint32_t sb = smem_u32(smem);
    int t = threadIdx.x;
    int wid = t >> 5, lane = t & 31;
    int wt = blockIdx.x;            // 0..3
    int nc = blockIdx.y;            // 0..1023
    int wbase = wt * 128;

    int mat = wid >> 3;             // 0: A -> x1, 1: A2 -> x2
    int nw  = (wid >> 2) & 1;       // n-group of 48
    int mw  = wid & 3;              // m-group of 32

    uint32_t aRow = (uint32_t)(mw * 32 + (lane & 15));
    uint32_t aKH  = (uint32_t)((lane >> 4) * 16);
    uint32_t xRow = (uint32_t)(nw * 48 + (lane & 7));
    uint32_t xKH  = (uint32_t)(((lane >> 3) & 1) * 16);

    float acc[2][6][4];
#pragma unroll
    for (int mi = 0; mi < 2; mi++)
#pragma unroll
        for (int ni = 0; ni < 6; ni++)
#pragma unroll
            for (int r = 0; r < 4; r++) acc[mi][ni][r] = 0.f;

    // prologue: stage 0 -> buffer 0
    {
        uint32_t b = sb;
        cp_tile(b + SM_AH, g_ATh, (size_t)wbase, 128, 0, t);
        cp_tile(b + SM_AL, g_ATl, (size_t)wbase, 128, 0, t);
        cp_tile(b + SM_BH, g_BTh, (size_t)wbase, 128, 0, t);
        cp_tile(b + SM_BL, g_BTl, (size_t)wbase, 128, 0, t);
        cp_tile(b + SM_XH, g_Xh, (size_t)nc * 96, 96, 0, t);
        cp_tile(b + SM_XL, g_Xl, (size_t)nc * 96, 96, 0, t);
        asm volatile("cp.async.commit_group;" ::: "memory");
    }

    for (int s = 0; s < 8; s++) {
        if (s < 7) {
            int kb = (s + 1) * 64;
            uint32_t b = sb + ((s + 1) & 1) * SM_STAGE;
            cp_tile(b + SM_AH, g_ATh, (size_t)wbase, 128, kb, t);
            cp_tile(b + SM_AL, g_ATl, (size_t)wbase, 128, kb, t);
            cp_tile(b + SM_BH, g_BTh, (size_t)wbase, 128, kb, t);
            cp_tile(b + SM_BL, g_BTl, (size_t)wbase, 128, kb, t);
            cp_tile(b + SM_XH, g_Xh, (size_t)nc * 96, 96, kb, t);
            cp_tile(b + SM_XL, g_Xl, (size_t)nc * 96, 96, kb, t);
            asm volatile("cp.async.commit_group;" ::: "memory");
            asm volatile("cp.async.wait_group 1;" ::: "memory");
        } else {
            asm volatile("cp.async.wait_group 0;" ::: "memory");
        }
        __syncthreads();

        uint32_t bufb = sb + (s & 1) * SM_STAGE;
        uint32_t aHbase = bufb + (mat ? SM_BH : SM_AH);
        uint32_t aLbase = bufb + (mat ? SM_BL : SM_AL);
        uint32_t xHbase = bufb + SM_XH;
        uint32_t xLbase = bufb + SM_XL;

#pragma unroll
        for (int ks = 0; ks < 4; ks++) {
            uint32_t kbyte = (uint32_t)(ks * 32);
            uint32_t ah[2][4], al[2][4];
#pragma unroll
            for (int mi = 0; mi < 2; mi++) {
                uint32_t bo = (aRow + mi * 16) * 128 + kbyte + aKH;
                uint32_t swo = sw128(bo);
                ldsm_x4(ah[mi][0], ah[mi][1], ah[mi][2], ah[mi][3], aHbase + swo);
                ldsm_x4(al[mi][0], al[mi][1], al[mi][2], al[mi][3], aLbase + swo);
            }
#pragma unroll
            for (int ni = 0; ni < 6; ni++) {
                uint32_t bo = (xRow + ni * 8) * 128 + kbyte + xKH;
                uint32_t swo = sw128(bo);
                uint32_t xh0, xh1, xl0, xl1;
                ldsm_x2(xh0, xh1, xHbase + swo);
                ldsm_x2(xl0, xl1, xLbase + swo);
#pragma unroll
                for (int mi = 0; mi < 2; mi++) {
                    mma16816(acc[mi][ni], ah[mi], xh0, xh1);
                    mma16816(acc[mi][ni], ah[mi], xl0, xl1);
                    mma16816(acc[mi][ni], al[mi], xh0, xh1);
                }
            }
        }
        __syncthreads();
    }

    // epilogue: d0,d1 -> row r, cols c,c+1 ; d2,d3 -> row r+8  (fp32 out)
    float* dst = (mat ? g_x2 : g_x1) + (size_t)nc * VV * LL;
    int r = lane >> 2, c = (lane & 3) * 2;
#pragma unroll
    for (int mi = 0; mi < 2; mi++) {
        int w0 = wbase + mw * 32 + mi * 16 + r;
#pragma unroll
        for (int ni = 0; ni < 6; ni++) {
            int l0 = nw * 48 + ni * 8 + c;
            if (l0 < LL) {
                if (w0 < VV)
                    *(float2*)&dst[(size_t)w0 * LL + l0] =
                        make_float2(acc[mi][ni][0], acc[mi][ni][1]);
                int w1 = w0 + 8;
                if (w1 < VV)
                    *(float2*)&dst[(size_t)w1 * LL + l0] =
                        make_float2(acc[mi][ni][2], acc[mi][ni][3]);
            }
        }
    }
}

// ---------------------------------------------------------------------------
// K3: projection as GEMM over contiguous columns j = v*94+l.  (FFMA2, R8)
// block: 64o x 128j, K=96 in 3 chunks of 32 mapping onto {xt, x1, x2}.
// ---------------------------------------------------------------------------
__global__ void __launch_bounds__(256) k_proj(
    const float* __restrict__ w_out, const float* __restrict__ b_out,
    const float* __restrict__ prelu_a, float* __restrict__ out)
{
    __shared__ __align__(16) float Wsm[GC][CO];    // 24576 B
    __shared__ __align__(16) float Hs[32][128];    // 16384 B
    int jb = blockIdx.x * 128;
    int n = blockIdx.y;
    int t = threadIdx.x;

    for (int e = t; e < GC * CO; e += 256) {
        int k = e >> 6, o = e & 63;
        Wsm[k][o] = w_out[o * GC + k];
    }

    int to = t >> 5, tj = t & 31;
    int ob = to * 8, jloc = tj * 4;
    u64 acc[4][4];
#pragma unroll
    for (int i = 0; i < 4; i++)
#pragma unroll
        for (int j = 0; j < 4; j++) acc[i][j] = 0ULL;

    for (int kc = 0; kc < 3; kc++) {
        const float* src = (kc == 0) ? g_xt : (kc == 1) ? g_x1 : g_x2;
        __syncthreads();
        for (int e = t; e < 32 * 128; e += 256) {
            int rr = e >> 7, j = e & 127;
            int gj = jb + j;
            Hs[rr][j] = (gj < JTOT) ? src[(size_t)(n * CC + rr) * JTOT + gj] : 0.f;
        }
        __syncthreads();
        int kbase = kc * 32;
#pragma unroll 4
        for (int kk = 0; kk < 32; kk++) {
            const u64* wr = (const u64*)&Wsm[kbase + kk][ob];
            u64 w0 = wr[0], w1 = wr[1], w2 = wr[2], w3 = wr[3];
            float4 hv = *(const float4*)&Hs[kk][jloc];
            u64 x0 = pk2(hv.x, hv.x), x1 = pk2(hv.y, hv.y);
            u64 x2 = pk2(hv.z, hv.z), x3 = pk2(hv.w, hv.w);
            ffma2(acc[0][0], w0, x0); ffma2(acc[0][1], w0, x1);
            ffma2(acc[0][2], w0, x2); ffma2(acc[0][3], w0, x3);
            ffma2(acc[1][0], w1, x0); ffma2(acc[1][1], w1, x1);
            ffma2(acc[1][2], w1, x2); ffma2(acc[1][3], w1, x3);
            ffma2(acc[2][0], w2, x0); ffma2(acc[2][1], w2, x1);
            ffma2(acc[2][2], w2, x2); ffma2(acc[2][3], w2, x3);
            ffma2(acc[3][0], w3, x0); ffma2(acc[3][1], w3, x1);
            ffma2(acc[3][2], w3, x2); ffma2(acc[3][3], w3, x3);
        }
    }

    float pa = prelu_a[0];
#pragma unroll
    for (int i = 0; i < 4; i++) {
        int o0 = ob + 2 * i, o1 = o0 + 1;
        float bo0 = b_out[o0], bo1 = b_out[o1];
        float* op0 = out + (size_t)(n * CO + o0) * JTOT;
        float* op1 = out + (size_t)(n * CO + o1) * JTOT;
#pragma unroll
        for (int j = 0; j < 4; j++) {
            int gj = jb + jloc + j;
            if (gj < JTOT) {
                float lo, hi;
                upk2(acc[i][j], lo, hi);
                float p0 = lo + bo0;
                float p1 = hi + bo1;
                op0[gj] = p0 > 0.f ? p0 : pa * p0;
                op1[gj] = p1 > 0.f ? p1 : pa * p1;
            }
        }
    }
}

// ---------------------------------------------------------------------------
extern "C" void kernel_launch(void* const* d_in, const int* in_sizes, int n_in,
                              void* d_out, int out_size)
{
    const float* x  = (const float*)d_in[0];
    const float* A  = (const float*)d_in[1];
    const float* w1 = (const float*)d_in[2];
    const float* b1 = (const float*)d_in[3];
    const float* w2 = (const float*)d_in[4];
    const float* b2 = (const float*)d_in[5];
    const float* w3 = (const float*)d_in[6];
    const float* b3 = (const float*)d_in[7];
    const float* wo = (const float*)d_in[8];
    const float* bo = (const float*)d_in[9];
    const float* pa = (const float*)d_in[10];
    float* out = (float*)d_out;

    static int smem_set = 0;
    if (!smem_set) {
        cudaFuncSetAttribute(k_diff_mma, cudaFuncAttributeMaxDynamicSharedMemorySize,
                             SM_DIFF_TOTAL);
        smem_set = 1;
    }

    k_a2<<<dim3(8, 8), 256>>>(A);
    k_prepA<<<(KPAD * KPAD) / 256, 256>>>(A);
    k_tconv<<<NB * VV, 256>>>(x, w1, b1, w2, b2, w3, b3);
    k_prepX<<<NC_TOT, 256>>>();
    k_diff_mma<<<dim3(4, NC_TOT), 512, SM_DIFF_TOTAL>>>();
    k_proj<<<dim3((JTOT + 127) / 128, NB), 256>>>(wo, bo, pa, out);
}

// round 13
// speedup vs baseline: 1.4109x; 1.1096x over previous
#include <cuda_runtime.h>
#include <cuda_bf16.h>
#include <math.h>
#include <stdint.h>

#define NB 32
#define CC 32
#define VV 500
#define TT 96
#define LL 94
#define CO 64
#define GC 96
#define NC_TOT (NB*CC)      // 1024
#define KPAD 512
#define JTOT (VV*LL)        // 47000

typedef unsigned long long u64;

// ---- packed f32x2 helpers (SASS FFMA2) ----
__device__ __forceinline__ u64 pk2(float lo, float hi) {
    u64 r; asm("mov.b64 %0, {%1, %2};" : "=l"(r) : "f"(lo), "f"(hi)); return r;
}
__device__ __forceinline__ void upk2(u64 v, float& lo, float& hi) {
    asm("mov.b64 {%0, %1}, %2;" : "=f"(lo), "=f"(hi) : "l"(v));
}
__device__ __forceinline__ void ffma2(u64& d, u64 a, u64 b) {
    asm("fma.rn.f32x2 %0, %1, %2, %3;" : "=l"(d) : "l"(a), "l"(b), "l"(d));
}

// ---- smem addr + ldmatrix + mma.sync + cp.async (portable sm_80+ PTX) ----
__device__ __forceinline__ uint32_t smem_u32(const void* p) {
    uint32_t a;
    asm("{ .reg .u64 t; cvta.to.shared.u64 t, %1; cvt.u32.u64 %0, t; }" : "=r"(a) : "l"(p));
    return a;
}
__device__ __forceinline__ uint32_t sw128(uint32_t o) { return o ^ ((o >> 3) & 0x70); }
// swizzle for 256-byte rows: chunk bits [7:4] ^= row bits [11:8]
__device__ __forceinline__ uint32_t sw256(uint32_t o) { return o ^ ((o >> 4) & 0xF0); }

__device__ __forceinline__ void ldsm_x4(uint32_t& a0, uint32_t& a1, uint32_t& a2, uint32_t& a3,
                                        uint32_t addr) {
    asm volatile("ldmatrix.sync.aligned.m8n8.x4.shared.b16 {%0,%1,%2,%3}, [%4];"
                 : "=r"(a0), "=r"(a1), "=r"(a2), "=r"(a3) : "r"(addr));
}
__device__ __forceinline__ void ldsm_x2(uint32_t& b0, uint32_t& b1, uint32_t addr) {
    asm volatile("ldmatrix.sync.aligned.m8n8.x2.shared.b16 {%0,%1}, [%2];"
                 : "=r"(b0), "=r"(b1) : "r"(addr));
}
__device__ __forceinline__ void ldsm_x2t(uint32_t& b0, uint32_t& b1, uint32_t addr) {
    asm volatile("ldmatrix.sync.aligned.m8n8.x2.trans.shared.b16 {%0,%1}, [%2];"
                 : "=r"(b0), "=r"(b1) : "r"(addr));
}
__device__ __forceinline__ void mma16816(float* d, const uint32_t* a, uint32_t b0, uint32_t b1) {
    asm volatile("mma.sync.aligned.m16n8k16.row.col.f32.bf16.bf16.f32 "
                 "{%0,%1,%2,%3},{%4,%5,%6,%7},{%8,%9},{%0,%1,%2,%3};"
                 : "+f"(d[0]), "+f"(d[1]), "+f"(d[2]), "+f"(d[3])
                 : "r"(a[0]), "r"(a[1]), "r"(a[2]), "r"(a[3]), "r"(b0), "r"(b1));
}
__device__ __forceinline__ void cpa16(uint32_t dst, const void* src) {
    asm volatile("cp.async.cg.shared.global [%0], [%1], 16;" :: "r"(dst), "l"(src));
}

// ---- scratch (static device globals; allocation-free) ----
__device__ float g_xt[48128000];   // (nc, v, l) fp32
__device__ float g_x1[48128000];
__device__ float g_x2[48128000];
__device__ float g_A2[VV * VV];
__device__ __align__(16) __nv_bfloat16 g_ATh[KPAD * KPAD];   // [w][v] hi
__device__ __align__(16) __nv_bfloat16 g_ATl[KPAD * KPAD];
__device__ __align__(16) __nv_bfloat16 g_BTh[KPAD * KPAD];   // A2
__device__ __align__(16) __nv_bfloat16 g_BTl[KPAD * KPAD];
__device__ __align__(16) __nv_bfloat16 g_Xh[(size_t)NC_TOT * 96 * KPAD]; // [nc][l][v]
__device__ __align__(16) __nv_bfloat16 g_Xl[(size_t)NC_TOT * 96 * KPAD];
__device__ __align__(16) __nv_bfloat16 g_Wh[CO * GC];
__device__ __align__(16) __nv_bfloat16 g_Wl[CO * GC];

// ---------------------------------------------------------------------------
// K0: A2 = A @ A
// ---------------------------------------------------------------------------
__global__ void __launch_bounds__(256) k_a2(const float* __restrict__ A)
{
    __shared__ __align__(16) float Ls[16][64];
    __shared__ __align__(16) float Rs[16][64];
    int rb = blockIdx.y * 64, wb = blockIdx.x * 64;
    int t = threadIdx.x;
    int tr = t >> 4, tw = t & 15;
    float acc[4][4];
#pragma unroll
    for (int i = 0; i < 4; i++)
#pragma unroll
        for (int j = 0; j < 4; j++) acc[i][j] = 0.f;

    for (int ub = 0; ub < 512; ub += 16) {
#pragma unroll
        for (int j = 0; j < 4; j++) {
            int e = t + j * 256;
            int uu = e & 15, r = e >> 4;
            int gr = rb + r, gu = ub + uu;
            Ls[uu][r] = (gr < VV && gu < VV) ? A[gr * VV + gu] : 0.f;
            int w = e & 63, uu2 = e >> 6;
            int gu2 = ub + uu2, gw = wb + w;
            Rs[uu2][w] = (gu2 < VV && gw < VV) ? A[gu2 * VV + gw] : 0.f;
        }
        __syncthreads();
#pragma unroll
        for (int uu = 0; uu < 16; uu++) {
            float4 lv = *(const float4*)&Ls[uu][tr * 4];
            float4 rv = *(const float4*)&Rs[uu][tw * 4];
            float l[4] = {lv.x, lv.y, lv.z, lv.w};
            float r[4] = {rv.x, rv.y, rv.z, rv.w};
#pragma unroll
            for (int i = 0; i < 4; i++)
#pragma unroll
                for (int j = 0; j < 4; j++) acc[i][j] += l[i] * r[j];
        }
        __syncthreads();
    }
#pragma unroll
    for (int i = 0; i < 4; i++) {
        int r = rb + tr * 4 + i;
        if (r < VV) {
#pragma unroll
            for (int j = 0; j < 4; j++) {
                int w = wb + tw * 4 + j;
                if (w < VV) g_A2[r * VV + w] = acc[i][j];
            }
        }
    }
}

// ---------------------------------------------------------------------------
// prepA: transposed, zero-padded bf16 hi/lo of A and A2: [w(512)][v(512)]
// ---------------------------------------------------------------------------
__global__ void __launch_bounds__(256) k_prepA(const float* __restrict__ A)
{
    int idx = blockIdx.x * 256 + threadIdx.x;
    if (idx >= KPAD * KPAD) return;
    int w = idx >> 9, v = idx & 511;
    bool ok = (v < VV) && (w < VV);
    float a = ok ? A[v * VV + w] : 0.f;
    float b = ok ? g_A2[v * VV + w] : 0.f;
    __nv_bfloat16 ah = __float2bfloat16(a);
    g_ATh[idx] = ah;
    g_ATl[idx] = __float2bfloat16(a - __bfloat162float(ah));
    __nv_bfloat16 bh = __float2bfloat16(b);
    g_BTh[idx] = bh;
    g_BTl[idx] = __float2bfloat16(b - __bfloat162float(bh));
}

// prepW: bf16 hi/lo of w_out [o][96]
__global__ void __launch_bounds__(256) k_prepW(const float* __restrict__ w_out)
{
    int e = blockIdx.x * 256 + threadIdx.x;
    if (e >= CO * GC) return;
    float v = w_out[e];
    __nv_bfloat16 h = __float2bfloat16(v);
    g_Wh[e] = h;
    g_Wl[e] = __float2bfloat16(v - __bfloat162float(h));
}

// ---------------------------------------------------------------------------
// K1: gated temporal conv (FFMA2) -> g_xt [nc][v][l]
// ---------------------------------------------------------------------------
__global__ void __launch_bounds__(256) k_tconv(const float* __restrict__ x,
    const float* __restrict__ w1, const float* __restrict__ b1,
    const float* __restrict__ w2, const float* __restrict__ b2,
    const float* __restrict__ w3, const float* __restrict__ b3)
{
    __shared__ __align__(16) float xs[CC][TT];
    __shared__ __align__(16) float ws[3][CC * 3 * CC];
    int nv = blockIdx.x;
    int n = nv / VV, v = nv - n * VV;
    int t = threadIdx.x;
    const float* xb = x + ((size_t)n * CC * VV + v) * TT;
    for (int e = t; e < CC * TT; e += 256) {
        int i = e / TT, tt = e - i * TT;
        xs[i][tt] = xb[(size_t)i * VV * TT + tt];
    }
    for (int e = t; e < CC * CC * 3; e += 256) {
        int c = e & 31;
        int ik = e >> 5;
        int i = ik / 3, k = ik - i * 3;
        int gi = (c * CC + i) * 3 + k;
        ws[0][e] = w1[gi];
        ws[1][e] = w2[gi];
        ws[2][e] = w3[gi];
    }
    __syncthreads();

    int c = t & 31, grp = t >> 5;
    int lb = grp * 12;
    u64 a1p[6], a2p[6], a3p[6];
#pragma unroll
    for (int j = 0; j < 6; j++) { a1p[j] = 0ULL; a2p[j] = 0ULL; a3p[j] = 0ULL; }

#pragma unroll 2
    for (int i = 0; i < CC; i++) {
        float xv[14];
#pragma unroll
        for (int j = 0; j < 14; j++)
            xv[j] = (lb + j < TT) ? xs[i][lb + j] : 0.f;
        u64 pa[7], pb[6];
#pragma unroll
        for (int j = 0; j < 7; j++) pa[j] = pk2(xv[2 * j], xv[2 * j + 1]);
#pragma unroll
        for (int j = 0; j < 6; j++) pb[j] = pk2(xv[2 * j + 1], xv[2 * j + 2]);
#pragma unroll
        for (int k = 0; k < 3; k++) {
            int wi = (i * 3 + k) * 32 + c;
            float wa = ws[0][wi], wb = ws[1][wi], wc = ws[2][wi];
            u64 wap = pk2(wa, wa), wbp = pk2(wb, wb), wcp = pk2(wc, wc);
#pragma unroll
            for (int j = 0; j < 6; j++) {
                u64 xp = (k == 0) ? pa[j] : (k == 1) ? pb[j] : pa[j + 1];
                ffma2(a1p[j], wap, xp);
                ffma2(a2p[j], wbp, xp);
                ffma2(a3p[j], wcp, xp);
            }
        }
    }
    float bb1 = b1[c], bb2 = b2[c], bb3 = b3[c];
    float* xo = g_xt + ((size_t)(n * CC + c) * VV + v) * LL;
#pragma unroll
    for (int j = 0; j < 6; j++) {
        float a1lo, a1hi, a2lo, a2hi, a3lo, a3hi;
        upk2(a1p[j], a1lo, a1hi);
        upk2(a2p[j], a2lo, a2hi);
        upk2(a3p[j], a3lo, a3hi);
        int l0 = lb + 2 * j;
        if (l0 < LL) {
            float z2 = a2lo + bb2;
            float sg = 1.f / (1.f + __expf(-z2));
            float tv = a1lo + bb1 + sg + a3lo + bb3;
            xo[l0] = fmaxf(tv, 0.f);
        }
        int l1 = l0 + 1;
        if (l1 < LL) {
            float z2 = a2hi + bb2;
            float sg = 1.f / (1.f + __expf(-z2));
            float tv = a1hi + bb1 + sg + a3hi + bb3;
            xo[l1] = fmaxf(tv, 0.f);
        }
    }
}

// ---------------------------------------------------------------------------
// prepX: transpose + bf16 hi/lo split of xt: [nc][l(96 pad)][v(512 pad)]
// ---------------------------------------------------------------------------
__global__ void __launch_bounds__(256) k_prepX()
{
    __shared__ float tile[32][33];
    int nc = blockIdx.x;
    int t = threadIdx.x;
    int tr = t >> 5, tc = t & 31;
    for (int lt = 0; lt < 3; lt++) {
        for (int vt = 0; vt < 16; vt++) {
            __syncthreads();
#pragma unroll
            for (int r = 0; r < 4; r++) {
                int vv = vt * 32 + tr + r * 8;
                int l = lt * 32 + tc;
                float val = (vv < VV && l < LL) ? g_xt[((size_t)nc * VV + vv) * LL + l] : 0.f;
                tile[tr + r * 8][tc] = val;
            }
            __syncthreads();
#pragma unroll
            for (int r = 0; r < 4; r++) {
                int l = lt * 32 + tr + r * 8;
                int vv = vt * 32 + tc;
                float val = tile[tc][tr + r * 8];
                __nv_bfloat16 h = __float2bfloat16(val);
                float lo = val - __bfloat162float(h);
                size_t o = ((size_t)nc * 96 + l) * KPAD + vv;
                g_Xh[o] = h;
                g_Xl[o] = __float2bfloat16(lo);
            }
        }
    }
}

// ---------------------------------------------------------------------------
// K2: mma.sync bf16-split diffusion, cp.async double-buffered. (R11, proven)
// ---------------------------------------------------------------------------
#define SM_AH   0
#define SM_AL   16384
#define SM_BH   32768
#define SM_BL   49152
#define SM_XH   65536
#define SM_XL   77824
#define SM_STAGE 90112
#define SM_DIFF_TOTAL (2 * SM_STAGE)   // 180224

__device__ __forceinline__ void cp_tile(uint32_t dstbase,
                                        const __nv_bfloat16* g, size_t rowbase,
                                        int nrows, int kb, int t)
{
    const uint4* gp = (const uint4*)g;
    for (int e = t; e < nrows * 8; e += 512) {
        int m = e >> 3, c8 = e & 7;
        const uint4* src = gp + (((rowbase + m) * KPAD + kb) >> 3) + c8;
        uint32_t bo = (uint32_t)m * 128 + c8 * 16;
        cpa16(dstbase + sw128(bo), src);
    }
}

__global__ void __launch_bounds__(512, 1) k_diff_mma()
{
    extern __shared__ char smem[];
    uint32_t sb = smem_u32(smem);
    int t = threadIdx.x;
    int wid = t >> 5, lane = t & 31;
    int wt = blockIdx.x;            // 0..3
    int nc = blockIdx.y;            // 0..1023
    int wbase = wt * 128;

    int mat = wid >> 3;             // 0: A -> x1, 1: A2 -> x2
    int nw  = (wid >> 2) & 1;       // n-group of 48
    int mw  = wid & 3;              // m-group of 32

    uint32_t aRow = (uint32_t)(mw * 32 + (lane & 15));
    uint32_t aKH  = (uint32_t)((lane >> 4) * 16);
    uint32_t xRow = (uint32_t)(nw * 48 + (lane & 7));
    uint32_t xKH  = (uint32_t)(((lane >> 3) & 1) * 16);

    float acc[2][6][4];
#pragma unroll
    for (int mi = 0; mi < 2; mi++)
#pragma unroll
        for (int ni = 0; ni < 6; ni++)
#pragma unroll
            for (int r = 0; r < 4; r++) acc[mi][ni][r] = 0.f;

    // prologue: stage 0 -> buffer 0
    {
        uint32_t b = sb;
        cp_tile(b + SM_AH, g_ATh, (size_t)wbase, 128, 0, t);
        cp_tile(b + SM_AL, g_ATl, (size_t)wbase, 128, 0, t);
        cp_tile(b + SM_BH, g_BTh, (size_t)wbase, 128, 0, t);
        cp_tile(b + SM_BL, g_BTl, (size_t)wbase, 128, 0, t);
        cp_tile(b + SM_XH, g_Xh, (size_t)nc * 96, 96, 0, t);
        cp_tile(b + SM_XL, g_Xl, (size_t)nc * 96, 96, 0, t);
        asm volatile("cp.async.commit_group;" ::: "memory");
    }

    for (int s = 0; s < 8; s++) {
        if (s < 7) {
            int kb = (s + 1) * 64;
            uint32_t b = sb + ((s + 1) & 1) * SM_STAGE;
            cp_tile(b + SM_AH, g_ATh, (size_t)wbase, 128, kb, t);
            cp_tile(b + SM_AL, g_ATl, (size_t)wbase, 128, kb, t);
            cp_tile(b + SM_BH, g_BTh, (size_t)wbase, 128, kb, t);
            cp_tile(b + SM_BL, g_BTl, (size_t)wbase, 128, kb, t);
            cp_tile(b + SM_XH, g_Xh, (size_t)nc * 96, 96, kb, t);
            cp_tile(b + SM_XL, g_Xl, (size_t)nc * 96, 96, kb, t);
            asm volatile("cp.async.commit_group;" ::: "memory");
            asm volatile("cp.async.wait_group 1;" ::: "memory");
        } else {
            asm volatile("cp.async.wait_group 0;" ::: "memory");
        }
        __syncthreads();

        uint32_t bufb = sb + (s & 1) * SM_STAGE;
        uint32_t aHbase = bufb + (mat ? SM_BH : SM_AH);
        uint32_t aLbase = bufb + (mat ? SM_BL : SM_AL);
        uint32_t xHbase = bufb + SM_XH;
        uint32_t xLbase = bufb + SM_XL;

#pragma unroll
        for (int ks = 0; ks < 4; ks++) {
            uint32_t kbyte = (uint32_t)(ks * 32);
            uint32_t ah[2][4], al[2][4];
#pragma unroll
            for (int mi = 0; mi < 2; mi++) {
                uint32_t bo = (aRow + mi * 16) * 128 + kbyte + aKH;
                uint32_t swo = sw128(bo);
                ldsm_x4(ah[mi][0], ah[mi][1], ah[mi][2], ah[mi][3], aHbase + swo);
                ldsm_x4(al[mi][0], al[mi][1], al[mi][2], al[mi][3], aLbase + swo);
            }
#pragma unroll
            for (int ni = 0; ni < 6; ni++) {
                uint32_t bo = (xRow + ni * 8) * 128 + kbyte + xKH;
                uint32_t swo = sw128(bo);
                uint32_t xh0, xh1, xl0, xl1;
                ldsm_x2(xh0, xh1, xHbase + swo);
                ldsm_x2(xl0, xl1, xLbase + swo);
#pragma unroll
                for (int mi = 0; mi < 2; mi++) {
                    mma16816(acc[mi][ni], ah[mi], xh0, xh1);
                    mma16816(acc[mi][ni], ah[mi], xl0, xl1);
                    mma16816(acc[mi][ni], al[mi], xh0, xh1);
                }
            }
        }
        __syncthreads();
    }

    // epilogue (fp32 out)
    float* dst = (mat ? g_x2 : g_x1) + (size_t)nc * VV * LL;
    int r = lane >> 2, c = (lane & 3) * 2;
#pragma unroll
    for (int mi = 0; mi < 2; mi++) {
        int w0 = wbase + mw * 32 + mi * 16 + r;
#pragma unroll
        for (int ni = 0; ni < 6; ni++) {
            int l0 = nw * 48 + ni * 8 + c;
            if (l0 < LL) {
                if (w0 < VV)
                    *(float2*)&dst[(size_t)w0 * LL + l0] =
                        make_float2(acc[mi][ni][0], acc[mi][ni][1]);
                int w1 = w0 + 8;
                if (w1 < VV)
                    *(float2*)&dst[(size_t)w1 * LL + l0] =
                        make_float2(acc[mi][ni][2], acc[mi][ni][3]);
            }
        }
    }
}

// ---------------------------------------------------------------------------
// K3: projection via mma.sync with in-kernel fp32->bf16 hi/lo conversion.
// out[o][j] = prelu(W[o,:96] . H[:,j] + b[o]),  H = [xt; x1; x2] fp32.
// block 256 thr / 8 warps, tile = 64o x 128j per (jb, n).
// ---------------------------------------------------------------------------
#define PJ 128
#define SMP_HH  0
#define SMP_HL  24576
#define SMP_WH  49152
#define SMP_WL  61440
#define SM_PROJ_TOTAL 73728
#define WS 192   // W smem row bytes (96 bf16)

__global__ void __launch_bounds__(256) k_proj_mma(
    const float* __restrict__ b_out, const float* __restrict__ prelu_a,
    float* __restrict__ out)
{
    extern __shared__ char smem[];
    uint32_t sb = smem_u32(smem);
    int t = threadIdx.x;
    int wid = t >> 5, lane = t & 31;
    int jb = blockIdx.x * PJ;
    int n = blockIdx.y;

    // stage W hi/lo (rows [o][k], 192B rows)
    for (int e = t; e < CO * GC; e += 256) {
        int o = e / GC, k = e - o * GC;
        *(__nv_bfloat16*)(smem + SMP_WH + o * WS + k * 2) = g_Wh[e];
        *(__nv_bfloat16*)(smem + SMP_WL + o * WS + k * 2) = g_Wl[e];
    }
    // stage H: load fp32, split to bf16 hi/lo, store into 256B swizzled rows
    for (int e = t; e < GC * 32; e += 256) {   // 96 rows x 32 float4
        int k = e >> 5, c4 = e & 31;
        int j0 = jb + c4 * 4;
        const float* src = (k < 32) ? g_xt : (k < 64) ? g_x1 : g_x2;
        int cc = k & 31;
        size_t gb = (size_t)(n * CC + cc) * JTOT + j0;
        float4 hv;
        if (j0 + 3 < JTOT) {
            hv = *(const float4*)(src + gb);
        } else {
            hv.x = (j0     < JTOT) ? src[gb]     : 0.f;
            hv.y = (j0 + 1 < JTOT) ? src[gb + 1] : 0.f;
            hv.z = (j0 + 2 < JTOT) ? src[gb + 2] : 0.f;
            hv.w = (j0 + 3 < JTOT) ? src[gb + 3] : 0.f;
        }
        __nv_bfloat16 h0 = __float2bfloat16(hv.x), h1 = __float2bfloat16(hv.y);
        __nv_bfloat16 h2 = __float2bfloat16(hv.z), h3 = __float2bfloat16(hv.w);
        __nv_bfloat16 l0 = __float2bfloat16(hv.x - __bfloat162float(h0));
        __nv_bfloat16 l1 = __float2bfloat16(hv.y - __bfloat162float(h1));
        __nv_bfloat16 l2 = __float2bfloat16(hv.z - __bfloat162float(h2));
        __nv_bfloat16 l3 = __float2bfloat16(hv.w - __bfloat162float(h3));
        uint32_t so = sw256((uint32_t)k * 256 + c4 * 8);
        *(__nv_bfloat162*)(smem + SMP_HH + so)     = __halves2bfloat162(h0, h1);
        *(__nv_bfloat162*)(smem + SMP_HH + so + 4) = __halves2bfloat162(h2, h3);
        *(__nv_bfloat162*)(smem + SMP_HL + so)     = __halves2bfloat162(l0, l1);
        *(__nv_bfloat162*)(smem + SMP_HL + so + 4) = __halves2bfloat162(l2, l3);
    }
    __syncthreads();

    int mt = wid & 3, nhalf = wid >> 2;

    // preload W fragments (m16k16, 6 ksteps, hi+lo)
    uint32_t wAddrRow = (uint32_t)(mt * 16 + (lane & 15)) * WS + ((lane >> 4) * 16);
    uint32_t ahf[6][4], alf[6][4];
#pragma unroll
    for (int kt = 0; kt < 6; kt++) {
        uint32_t ad = wAddrRow + kt * 32;
        ldsm_x4(ahf[kt][0], ahf[kt][1], ahf[kt][2], ahf[kt][3], sb + SMP_WH + ad);
        ldsm_x4(alf[kt][0], alf[kt][1], alf[kt][2], alf[kt][3], sb + SMP_WL + ad);
    }

    float acc[8][4];
#pragma unroll
    for (int i = 0; i < 8; i++)
#pragma unroll
        for (int r = 0; r < 4; r++) acc[i][r] = 0.f;

    uint32_t bRow = (uint32_t)(lane & 15);   // k row within kstep
#pragma unroll
    for (int kt = 0; kt < 6; kt++) {
        uint32_t krow = (uint32_t)(kt * 16) + bRow;
#pragma unroll
        for (int nt = 0; nt < 8; nt++) {
            uint32_t bo = sw256(krow * 256 + (uint32_t)(nhalf * 64 + nt * 8) * 2);
            uint32_t bh0, bh1, bl0, bl1;
            ldsm_x2t(bh0, bh1, sb + SMP_HH + bo);
            ldsm_x2t(bl0, bl1, sb + SMP_HL + bo);
            mma16816(acc[nt], ahf[kt], bh0, bh1);
            mma16816(acc[nt], ahf[kt], bl0, bl1);
            mma16816(acc[nt], alf[kt], bh0, bh1);
        }
    }

    // epilogue: bias + PReLU
    float pa = prelu_a[0];
    int r = lane >> 2, cc2 = (lane & 3) * 2;
    int o0 = mt * 16 + r, o1 = o0 + 8;
    float bo0 = b_out[o0], bo1 = b_out[o1];
    float* ob0 = out + (size_t)(n * CO + o0) * JTOT;
    float* ob1 = out + (size_t)(n * CO + o1) * JTOT;
#pragma unroll
    for (int nt = 0; nt < 8; nt++) {
        int j0 = jb + nhalf * 64 + nt * 8 + cc2;
        if (j0 < JTOT) {
            float p0 = acc[nt][0] + bo0;
            float p1 = acc[nt][1] + bo0;
            *(float2*)&ob0[j0] = make_float2(p0 > 0.f ? p0 : pa * p0,
                                             p1 > 0.f ? p1 : pa * p1);
            float p2 = acc[nt][2] + bo1;
            float p3 = acc[nt][3] + bo1;
            *(float2*)&ob1[j0] = make_float2(p2 > 0.f ? p2 : pa * p2,
                                             p3 > 0.f ? p3 : pa * p3);
        }
    }
}

// ---------------------------------------------------------------------------
extern "C" void kernel_launch(void* const* d_in, const int* in_sizes, int n_in,
                              void* d_out, int out_size)
{
    const float* x  = (const float*)d_in[0];
    const float* A  = (const float*)d_in[1];
    const float* w1 = (const float*)d_in[2];
    const float* b1 = (const float*)d_in[3];
    const float* w2 = (const float*)d_in[4];
    const float* b2 = (const float*)d_in[5];
    const float* w3 = (const float*)d_in[6];
    const float* b3 = (const float*)d_in[7];
    const float* wo = (const float*)d_in[8];
    const float* bo = (const float*)d_in[9];
    const float* pa = (const float*)d_in[10];
    float* out = (float*)d_out;

    static int smem_set = 0;
    if (!smem_set) {
        cudaFuncSetAttribute(k_diff_mma, cudaFuncAttributeMaxDynamicSharedMemorySize,
                             SM_DIFF_TOTAL);
        cudaFuncSetAttribute(k_proj_mma, cudaFuncAttributeMaxDynamicSharedMemorySize,
                             SM_PROJ_TOTAL);
        smem_set = 1;
    }

    k_a2<<<dim3(8, 8), 256>>>(A);
    k_prepA<<<(KPAD * KPAD) / 256, 256>>>(A);
    k_prepW<<<(CO * GC + 255) / 256, 256>>>(wo);
    k_tconv<<<NB * VV, 256>>>(x, w1, b1, w2, b2, w3, b3);
    k_prepX<<<NC_TOT, 256>>>();
    k_diff_mma<<<dim3(4, NC_TOT), 512, SM_DIFF_TOTAL>>>();
    k_proj_mma<<<dim3((JTOT + PJ - 1) / PJ, NB), 256, SM_PROJ_TOTAL>>>(bo, pa, out);
}